// round 2
// baseline (speedup 1.0000x reference)
#include <cuda_runtime.h>
#include <math.h>

#define NB   4
#define SEQ  2048
#define DIMD 1024
#define PQ   512
#define NH   16
#define PD   64

// ---- static device scratch (no allocations allowed) ----
static __device__ float g_xds[NB * PQ * DIMD];            // pooled x  [2048][1024]
static __device__ float g_q  [NB * PQ * DIMD];
static __device__ float g_k  [NB * PQ * DIMD];
static __device__ float g_pA [DIMD];
static __device__ float g_pB [DIMD];
static __device__ float g_yq [NB * PQ * PD];
static __device__ float g_yk [NB * PQ * PD];
static __device__ float g_RqA[NB * PQ * PD];
static __device__ float g_RqB[NB * PQ * PD];
static __device__ float g_CkA[NB * PQ * PD];
static __device__ float g_CkB[NB * PQ * PD];
static __device__ float g_dot[(size_t)NB * NH * PQ * PQ]; // [b][h][q][k]

// ---------------- 1) avg-pool (POOL=4) ----------------
__global__ void k_pool(const float* __restrict__ x) {
    int gid = blockIdx.x * blockDim.x + threadIdx.x;  // 2048*256
    int d4 = gid & 255;
    int bp = gid >> 8;                                // b*512+p
    const float4* xin = reinterpret_cast<const float4*>(x);
    size_t base = (size_t)bp * 4 * 256 + d4;          // row b*2048+4p
    float4 r0 = xin[base];
    float4 r1 = xin[base + 256];
    float4 r2 = xin[base + 512];
    float4 r3 = xin[base + 768];
    float4 o;
    o.x = (r0.x + r1.x + r2.x + r3.x) * 0.25f;
    o.y = (r0.y + r1.y + r2.y + r3.y) * 0.25f;
    o.z = (r0.z + r1.z + r2.z + r3.z) * 0.25f;
    o.w = (r0.w + r1.w + r2.w + r3.w) * 0.25f;
    reinterpret_cast<float4*>(g_xds)[(size_t)bp * 256 + d4] = o;
}

// ---------------- 2) pos_enc collapse: two vectors ----------------
__global__ void k_posenc(const float* __restrict__ Wpos, const float* __restrict__ bpos) {
    int hc = blockIdx.x * blockDim.x + threadIdx.x;
    if (hc >= DIMD) return;
    float s1 = 0.f, s2 = 0.f;
#pragma unroll
    for (int j = 0; j < 32; j++) s1 += Wpos[hc * 64 + j];
#pragma unroll
    for (int j = 32; j < 64; j++) s2 += Wpos[hc * 64 + j];
    g_pA[hc] = s1 - s2 + bpos[hc];   // p < 511
    g_pB[hc] = s1 + bpos[hc];        // p == 511
}

// ---------------- 3) q/k projection SGEMM: [2048x1024]@[1024x1024]^T ----------------
__global__ __launch_bounds__(256) void k_proj(const float* __restrict__ Wq,
                                              const float* __restrict__ Wk) {
    __shared__ float As[8][132];
    __shared__ float Bs[8][132];
    const float* __restrict__ A = g_xds;
    const float* __restrict__ B = blockIdx.z ? Wk : Wq;
    float* __restrict__ C = blockIdx.z ? g_k : g_q;
    int bm = blockIdx.y * 128;
    int bn = blockIdx.x * 128;
    int tid = threadIdx.x;
    int lr = tid >> 1;
    int lc = (tid & 1) * 4;
    int tx = tid & 15;
    int ty = tid >> 4;
    float acc[8][8];
#pragma unroll
    for (int i = 0; i < 8; i++)
#pragma unroll
        for (int j = 0; j < 8; j++) acc[i][j] = 0.f;

    for (int k0 = 0; k0 < DIMD; k0 += 8) {
        float4 av = *(const float4*)&A[(size_t)(bm + lr) * DIMD + k0 + lc];
        float4 bv = *(const float4*)&B[(size_t)(bn + lr) * DIMD + k0 + lc];
        __syncthreads();
        As[lc + 0][lr] = av.x; As[lc + 1][lr] = av.y;
        As[lc + 2][lr] = av.z; As[lc + 3][lr] = av.w;
        Bs[lc + 0][lr] = bv.x; Bs[lc + 1][lr] = bv.y;
        Bs[lc + 2][lr] = bv.z; Bs[lc + 3][lr] = bv.w;
        __syncthreads();
#pragma unroll
        for (int kk = 0; kk < 8; kk++) {
            float af[8], bf[8];
#pragma unroll
            for (int i = 0; i < 8; i++) af[i] = As[kk][ty + 16 * i];
#pragma unroll
            for (int j = 0; j < 8; j++) bf[j] = Bs[kk][tx + 16 * j];
#pragma unroll
            for (int i = 0; i < 8; i++)
#pragma unroll
                for (int j = 0; j < 8; j++) acc[i][j] += af[i] * bf[j];
        }
    }
#pragma unroll
    for (int i = 0; i < 8; i++) {
        size_t m = (size_t)(bm + ty + 16 * i);
#pragma unroll
        for (int j = 0; j < 8; j++)
            C[m * DIMD + bn + tx + 16 * j] = acc[i][j];
    }
}

// ---------------- 4) yq/yk = gelu(x_ds) @ Wy^T ----------------
__global__ __launch_bounds__(256) void k_y(const float* __restrict__ Wyq,
                                           const float* __restrict__ Wyk) {
    __shared__ float gs[8][1024];
    __shared__ float red[4][8][64];
    const float* __restrict__ W = blockIdx.z ? Wyk : Wyq;
    float* __restrict__ Y = blockIdx.z ? g_yk : g_yq;
    int row0 = blockIdx.x * 8;
    int tid = threadIdx.x;
    const float4* src = reinterpret_cast<const float4*>(g_xds) + (size_t)row0 * 256;
#pragma unroll
    for (int it = 0; it < 8; it++) {
        int idx = it * 256 + tid;
        int r = idx >> 8, c4 = idx & 255;
        float4 v = src[(size_t)r * 256 + c4];
        v.x = 0.5f * v.x * (1.f + erff(v.x * 0.70710678f));
        v.y = 0.5f * v.y * (1.f + erff(v.y * 0.70710678f));
        v.z = 0.5f * v.z * (1.f + erff(v.z * 0.70710678f));
        v.w = 0.5f * v.w * (1.f + erff(v.w * 0.70710678f));
        *(float4*)&gs[r][c4 * 4] = v;
    }
    __syncthreads();
    int d = tid & 63;
    int ks = tid >> 6;     // K slice 0..3
    float acc[8];
#pragma unroll
    for (int m = 0; m < 8; m++) acc[m] = 0.f;
    const float* wr = &W[(size_t)d * DIMD + ks * 256];
#pragma unroll 4
    for (int k4 = 0; k4 < 64; k4++) {
        float4 w = *(const float4*)&wr[k4 * 4];
        int k = ks * 256 + k4 * 4;
#pragma unroll
        for (int m = 0; m < 8; m++) {
            float4 g = *(const float4*)&gs[m][k];
            acc[m] += g.x * w.x + g.y * w.y + g.z * w.z + g.w * w.w;
        }
    }
#pragma unroll
    for (int m = 0; m < 8; m++) red[ks][m][d] = acc[m];
    __syncthreads();
    if (tid < 64) {
#pragma unroll
        for (int m = 0; m < 8; m++)
            Y[(size_t)(row0 + m) * 64 + tid] =
                red[0][m][tid] + red[1][m][tid] + red[2][m][tid] + red[3][m][tid];
    }
}

// ---------------- 5) row/col correction tensors ----------------
__global__ __launch_bounds__(64) void k_scalars(const float* __restrict__ qbias,
                                                const float* __restrict__ kbias,
                                                const float* __restrict__ Wout,
                                                const float* __restrict__ bout) {
    __shared__ float sA[16], sB[16];
    int row = blockIdx.x;          // b*512 + p
    int z = blockIdx.y;            // 0: Rq (from q), 1: Ck (from k)
    const float* src  = z ? g_k : g_q;
    const float* bias = z ? kbias : qbias;
    const float* y    = z ? g_yk : g_yq;
    int t = threadIdx.x;
    if (t < 16) {
        float a = 0.f, bs = 0.f;
        int base = t * 64;
        for (int c = 0; c < 64; c++) {
            float v = src[(size_t)row * DIMD + base + c] + bias[base + c];
            a  += v * g_pA[base + c];
            bs += v * g_pB[base + c];
        }
        sA[t] = a; sB[t] = bs;
    }
    __syncthreads();
    float rA = 0.f, rB = 0.f;
#pragma unroll
    for (int h = 0; h < 16; h++) {
        float w = Wout[t * 16 + h];
        rA += sA[h] * w;
        rB += sB[h] * w;
    }
    float extra = y[(size_t)row * 64 + t] + (z ? 0.f : bout[t]);
    rA = 0.5f * rA + extra;
    rB = 0.5f * rB + extra;
    if (z == 0) { g_RqA[(size_t)row * 64 + t] = rA; g_RqB[(size_t)row * 64 + t] = rB; }
    else        { g_CkA[(size_t)row * 64 + t] = rA; g_CkB[(size_t)row * 64 + t] = rB; }
}

// ---------------- 6) dot GEMM per (b,h): 512x512x64 ----------------
__global__ __launch_bounds__(256) void k_dot() {
    __shared__ float Qs[32][129];
    __shared__ float Ks[32][129];
    int bh = blockIdx.z;
    int b = bh >> 4, h = bh & 15;
    int bm = blockIdx.y * 128;   // q
    int bn = blockIdx.x * 128;   // k
    int tid = threadIdx.x;
    int tx = tid & 15, ty = tid >> 4;
    float acc[8][8];
#pragma unroll
    for (int i = 0; i < 8; i++)
#pragma unroll
        for (int j = 0; j < 8; j++) acc[i][j] = 0.f;
    const float* qbase = g_q + ((size_t)(b * PQ + bm) * NH + h) * PD;
    const float* kbase = g_k + ((size_t)(b * PQ + bn) * NH + h) * PD;
    for (int ks0 = 0; ks0 < 64; ks0 += 32) {
        __syncthreads();
#pragma unroll
        for (int it = 0; it < 4; it++) {
            int idx = it * 256 + tid;
            int r = idx >> 3, c4 = idx & 7;
            float4 qv = *(const float4*)&qbase[(size_t)r * (NH * PD) + ks0 + c4 * 4];
            float4 kv = *(const float4*)&kbase[(size_t)r * (NH * PD) + ks0 + c4 * 4];
            Qs[c4 * 4 + 0][r] = qv.x; Qs[c4 * 4 + 1][r] = qv.y;
            Qs[c4 * 4 + 2][r] = qv.z; Qs[c4 * 4 + 3][r] = qv.w;
            Ks[c4 * 4 + 0][r] = kv.x; Ks[c4 * 4 + 1][r] = kv.y;
            Ks[c4 * 4 + 2][r] = kv.z; Ks[c4 * 4 + 3][r] = kv.w;
        }
        __syncthreads();
#pragma unroll
        for (int kk = 0; kk < 32; kk++) {
            float af[8], bf[8];
#pragma unroll
            for (int i = 0; i < 8; i++) af[i] = Qs[kk][ty + 16 * i];
#pragma unroll
            for (int j = 0; j < 8; j++) bf[j] = Ks[kk][tx + 16 * j];
#pragma unroll
            for (int i = 0; i < 8; i++)
#pragma unroll
                for (int j = 0; j < 8; j++) acc[i][j] += af[i] * bf[j];
        }
    }
    float* out = g_dot + ((size_t)(b * NH + h) * PQ + bm) * PQ + bn;
#pragma unroll
    for (int i = 0; i < 8; i++)
#pragma unroll
        for (int j = 0; j < 8; j++)
            out[(size_t)(ty + 16 * i) * PQ + tx + 16 * j] = acc[i][j];
}

// ---------------- 7) epilogue: pair = dot@Wout^T + Rq + Ck ----------------
__global__ __launch_bounds__(256) void k_epilogue(const float* __restrict__ Wout,
                                                  float* __restrict__ out) {
    __shared__ float As[16][512];
    int q = blockIdx.x;
    int b = blockIdx.y;
    int tid = threadIdx.x;
#pragma unroll
    for (int it = 0; it < 8; it++) {
        int idx = it * 256 + tid;            // over 16 h x 128 float4
        int h = idx >> 7, k4 = idx & 127;
        float4 v = *(const float4*)(g_dot + ((size_t)(b * NH + h) * PQ + q) * PQ + k4 * 4);
        *(float4*)&As[h][k4 * 4] = v;
    }
    __syncthreads();
    int dp = tid & 31;
    int kk = tid >> 5;      // 0..7
    int d0 = dp, d1 = dp + 32;
    float w0[16], w1[16];
#pragma unroll
    for (int h = 0; h < 16; h++) {
        w0[h] = Wout[d0 * 16 + h];
        w1[h] = Wout[d1 * 16 + h];
    }
    size_t rowq = (size_t)b * PQ + q;
    float rqA0 = g_RqA[rowq * 64 + d0], rqA1 = g_RqA[rowq * 64 + d1];
    float rqB0 = g_RqB[rowq * 64 + d0], rqB1 = g_RqB[rowq * 64 + d1];
    const float* ck = (q == PQ - 1 ? g_CkB : g_CkA) + (size_t)b * PQ * 64;
    float* obase = out + rowq * PQ * 64;
    for (int it = 0; it < 64; it++) {
        int k = it * 8 + kk;
        float a0 = 0.f, a1 = 0.f;
#pragma unroll
        for (int h = 0; h < 16; h++) {
            float av = As[h][k];
            a0 += av * w0[h];
            a1 += av * w1[h];
        }
        float rq0 = (k == PQ - 1) ? rqB0 : rqA0;
        float rq1 = (k == PQ - 1) ? rqB1 : rqA1;
        obase[(size_t)k * 64 + d0] = a0 + rq0 + ck[(size_t)k * 64 + d0];
        obase[(size_t)k * 64 + d1] = a1 + rq1 + ck[(size_t)k * 64 + d1];
    }
}

extern "C" void kernel_launch(void* const* d_in, const int* in_sizes, int n_in,
                              void* d_out, int out_size) {
    const float* x    = (const float*)d_in[0];
    const float* Wq   = (const float*)d_in[1];
    const float* Wk   = (const float*)d_in[2];
    const float* Wpos = (const float*)d_in[3];
    const float* bpos = (const float*)d_in[4];
    const float* qb   = (const float*)d_in[5];
    const float* kb   = (const float*)d_in[6];
    const float* Wout = (const float*)d_in[7];
    const float* bout = (const float*)d_in[8];
    const float* Wyq  = (const float*)d_in[9];
    const float* Wyk  = (const float*)d_in[10];
    float* out = (float*)d_out;
    (void)in_sizes; (void)n_in; (void)out_size;

    k_pool   <<<2048, 256>>>(x);
    k_posenc <<<4, 256>>>(Wpos, bpos);
    k_proj   <<<dim3(8, 16, 2), 256>>>(Wq, Wk);
    k_y      <<<dim3(256, 1, 2), 256>>>(Wyq, Wyk);
    k_scalars<<<dim3(2048, 2), 64>>>(qb, kb, Wout, bout);
    k_dot    <<<dim3(4, 4, 64), 256>>>();
    k_epilogue<<<dim3(512, 4), 256>>>(Wout, out);
}